// round 8
// baseline (speedup 1.0000x reference)
#include <cuda_runtime.h>
#include <stdint.h>

// ---------------- problem constants ----------------
#define NC    80
#define A0    4096
#define A1    1024
#define A2    256
#define N0    (A0*NC)          // 327680
#define N1    (A1*NC)          // 81920
#define N2    (A2*NC)          // 20480
#define TOT   (N0+N1+N2)       // 430080 per image
#define OFF1  N0
#define OFF2  (N0+N1)
#define NB    8
#define TOPK  1000
#define NLVL  3
#define NPAIR (NB*NLVL)        // 24
#define CAND  3000
#define DETS  100
#define IMGSZ 2048.0f
#define NMS_T 0.6f
#define CAP   4096
#define BINS  16512            // key16 range: ~f2k(w>=1) >> 16 in [127, 16511]
#define WCAP  128              // fast-path capacity per class (avg ~37)
#define CHUNK 94               // ranks per warp in counting sort (32*94 >= 3000)

// dynamic smem for k_sortlevel: union of hist (BINS u32) and sort buffer (CAP u64)
#define DYNBYTES ((BINS*4 > CAP*8) ? BINS*4 : CAP*8)

// k_post dynamic smem layout (bytes)
#define PO_SC     0          // float sc[3008]
#define PO_SS     12032      // float ss[3008]
#define PO_WOFS   24064      // u32 wofs[32*80]
#define PO_SMASK  34304      // u32 smask[32*WCAP*4]
#define PO_CCLS   99840      // u32 ccls[80]
#define PO_CSTART 100160     // u32 cstart[80]
#define PO_R2P    100480     // u16 r2p[3008]
#define PO_CORD   106496     // u16 cord[3008]
#define PO_LABT   112512     // u8 labt[3008]
#define PO_KEEP   115520     // u8 keepr[3008]
#define POSTBYTES 118528

// ---------------- scratch (device globals; no allocations) ----------------
__device__ __align__(16) unsigned short g_keys16[NB*TOT]; // ~6.9 MB
__device__ float    g_score[NB*CAND];
__device__ int      g_labelv[NB*CAND];
__device__ float    g_boxv[NB*CAND*4];

// ---------------- helpers ----------------
__device__ __forceinline__ uint32_t f2k(float f){
    uint32_t u = __float_as_uint(f);
    return (u & 0x80000000u) ? ~u : (u | 0x80000000u);
}
__device__ __forceinline__ float k2f(uint32_t k){
    uint32_t u = (k & 0x80000000u) ? (k ^ 0x80000000u) : ~k;
    return __uint_as_float(u);
}
// exact path: XLA logistic(x) == 0.5 + 0.5*tanh(0.5*x)
__device__ __forceinline__ float sigm(float x){
    return 0.5f*tanhf(0.5f*x) + 0.5f;
}
__device__ __forceinline__ float pick4(const float a[4], int s){
    float v = a[0];
    v = (s == 1) ? a[1] : v;
    v = (s == 2) ? a[2] : v;
    v = (s == 3) ? a[3] : v;
    return v;
}

// bitonic sort (ascending) of n (2048 or 4096) u64s, blockDim = 1024
__device__ __forceinline__ void bitonicN(unsigned long long* s, int n){
    const int tid = threadIdx.x;
    const int per = n >> 10;
    for (int k = 2; k <= n; k <<= 1){
        for (int j = k >> 1; j > 0; j >>= 1){
            __syncthreads();
            for (int w = 0; w < per; ++w){
                int i   = tid + (w << 10);
                int ixj = i ^ j;
                if (ixj > i){
                    unsigned long long a = s[i], bb = s[ixj];
                    bool up = ((i & k) == 0);
                    if ((a > bb) == up){ s[i] = bb; s[ixj] = a; }
                }
            }
        }
    }
    __syncthreads();
}

// ---------------- kernels ----------------
// pure streaming pass: surrogate 16-bit keys, NO atomics
// surrogate: w = (1+e^-c)(1+e^-t); score order == descending w (monotone)
__global__ __launch_bounds__(256) void k_scores(
    const float* __restrict__ cls0, const float* __restrict__ cls1, const float* __restrict__ cls2,
    const float* __restrict__ ctr0, const float* __restrict__ ctr1, const float* __restrict__ ctr2)
{
    const int b = blockIdx.y;
    const int base = blockIdx.x*2048 + threadIdx.x*8;   // blocks never straddle levels; 8-runs never straddle anchors
    int j0, A; const float* cls; const float* ctr;
    if (base < OFF1){ j0 = base;        cls = cls0; ctr = ctr0; A = A0; }
    else if (base < OFF2){ j0 = base - OFF1; cls = cls1; ctr = ctr1; A = A1; }
    else { j0 = base - OFF2; cls = cls2; ctr = ctr2; A = A2; }

    float tv = __ldg(ctr + (size_t)b*A + j0/NC);
    float et = __expf(-tv);
    float vt = et + 1.0f;

    const float4* cp = (const float4*)(cls + (size_t)b*A*NC + j0);
    float4 ca = cp[0], cb = cp[1];
    float cv[8] = {ca.x, ca.y, ca.z, ca.w, cb.x, cb.y, cb.z, cb.w};

    uint32_t ks[8];
    #pragma unroll
    for (int e = 0; e < 8; ++e){
        float ec = __expf(-cv[e]);
        float w  = fmaf(ec, vt, vt);                        // (1+ec)*vt
        ks[e] = ((~__float_as_uint(w)) & 0x7FFFFFFFu) >> 16; // = ~f2k(w)>>16, w>0
    }
    uint4 pk;
    pk.x = ks[0] | (ks[1] << 16);
    pk.y = ks[2] | (ks[3] << 16);
    pk.z = ks[4] | (ks[5] << 16);
    pk.w = ks[6] | (ks[7] << 16);
    *(uint4*)(g_keys16 + (size_t)b*TOT + base) = pk;
}

// per (image,level): shared hist + pivot + collect + exact rescore + sort + decode top-1000
__global__ __launch_bounds__(1024) void k_sortlevel(
    const float* __restrict__ cls0, const float* __restrict__ cls1, const float* __restrict__ cls2,
    const float* __restrict__ ctr0, const float* __restrict__ ctr1, const float* __restrict__ ctr2,
    const float* __restrict__ reg0, const float* __restrict__ reg1, const float* __restrict__ reg2,
    const float* __restrict__ anc0, const float* __restrict__ anc1, const float* __restrict__ anc2)
{
    extern __shared__ unsigned char dynsmem[];
    uint32_t*           hist = (uint32_t*)dynsmem;           // phase A (BINS u32)
    unsigned long long* s64  = (unsigned long long*)dynsmem; // phase B+ (CAP u64), aliases hist
    __shared__ uint32_t ssum[1024];
    __shared__ int sP, sCum, sThresh, sCnt;

    const int p = blockIdx.x, b = p/NLVL, l = p%NLVL;
    const int tid = threadIdx.x;
    int A, offl; const float *cls, *ctr, *reg, *anc;
    if (l == 0){ A=A0; offl=0;    cls=cls0; ctr=ctr0; reg=reg0; anc=anc0; }
    else if (l == 1){ A=A1; offl=OFF1; cls=cls1; ctr=ctr1; reg=reg1; anc=anc1; }
    else { A=A2; offl=OFF2; cls=cls2; ctr=ctr2; reg=reg2; anc=anc2; }

    // ---- phase H: build local histogram from this pair's key slice (L2-resident)
    for (int t = tid; t < BINS; t += 1024) hist[t] = 0;
    __syncthreads();
    const uint4* kp = (const uint4*)(g_keys16 + (size_t)b*TOT + offl);
    const int num8 = (A*NC)/8;
    for (int v = tid; v < num8; v += 1024){
        uint4 q = kp[v];
        uint32_t wv[4] = {q.x, q.y, q.z, q.w};
        #pragma unroll
        for (int u = 0; u < 4; ++u){
            atomicAdd(hist + (wv[u] & 0xFFFFu), 1u);
            atomicAdd(hist + (wv[u] >> 16),     1u);
        }
    }
    __syncthreads();

    // ---- phase A: pivot bin (highest T with cum(bins>=T) >= TOPK), extend 1 bin if safe
    int lo = tid*17; if (lo > BINS) lo = BINS;
    int hi = lo + 17; if (hi > BINS) hi = BINS;
    uint32_t own = 0;
    for (int i = lo; i < hi; ++i) own += hist[i];
    ssum[tid] = own; __syncthreads();
    for (int off = 1; off < 1024; off <<= 1){
        uint32_t v = (tid + off < 1024) ? ssum[tid + off] : 0;
        __syncthreads(); ssum[tid] += v; __syncthreads();
    }
    uint32_t cumAbove = (tid < 1023) ? ssum[tid + 1] : 0;
    if (tid == 0) sCnt = 0;
    if (cumAbove < TOPK && cumAbove + own >= TOPK){
        uint32_t run = cumAbove; int P = lo;
        for (int i = hi - 1; i >= lo; --i){ run += hist[i]; if (run >= TOPK){ P = i; break; } }
        sP = P; sCum = (int)run;
    }
    __syncthreads();
    if (tid == 0){
        int P = sP, ext = P;
        if (P > 0 && sCum + (int)hist[P-1] <= CAP) ext = P - 1;
        sThresh = ext;
    }
    __syncthreads();
    const uint32_t thr = (uint32_t)sThresh;
    __syncthreads();   // all hist reads done before s64 overwrites it

    // ---- phase B: collect candidate indices (order arbitrary; fixed by sort)
    for (int v = tid; v < num8; v += 1024){
        uint4 q = kp[v];
        uint32_t wv[4] = {q.x, q.y, q.z, q.w};
        #pragma unroll
        for (int u = 0; u < 4; ++u){
            uint32_t l16 = wv[u] & 0xFFFFu, h16 = wv[u] >> 16;
            if (l16 >= thr){ int pos = atomicAdd(&sCnt, 1); if (pos < CAP) s64[pos] = (unsigned long long)(v*8 + u*2); }
            if (h16 >= thr){ int pos = atomicAdd(&sCnt, 1); if (pos < CAP) s64[pos] = (unsigned long long)(v*8 + u*2 + 1); }
        }
    }
    __syncthreads();
    int cnt = sCnt; if (cnt > CAP) cnt = CAP;
    const int SORTN = (cnt <= 2048) ? 2048 : 4096;

    // ---- phase C: exact XLA-matching scores; build (~key, idx) composites
    for (int i = tid; i < SORTN; i += 1024){
        unsigned long long comp = 0xFFFFFFFFFFFFFFFFULL;
        if (i < cnt){
            int j = (int)(uint32_t)s64[i];
            float c  = cls[(size_t)b*A*NC + j];
            float tt = ctr[(size_t)b*A + j/NC];
            float sa = sigm(c);
            float st = sigm(tt);
            float sc = sqrtf(__fmul_rn(sa, st));
            uint32_t key = (sc > 0.2f) ? f2k(sc) : 0x407FFFFFu;   // f2k(-1.0f)
            comp = ((unsigned long long)(~key) << 32) | (uint32_t)j;
        }
        s64[i] = comp;
    }
    bitonicN(s64, SORTN);

    // ---- phase E: emit sorted top-1000 + decode boxes
    if (tid < TOPK){
        unsigned long long cc = s64[tid];
        uint32_t key = ~(uint32_t)(cc >> 32);
        uint32_t idx = (uint32_t)cc;
        float sc = k2f(key);
        int aidx = (int)(idx / NC);
        int lab  = (int)(idx % NC);

        const int pos = b*CAND + l*TOPK + tid;
        g_score[pos]  = sc;
        g_labelv[pos] = lab;

        const float* a = anc + (size_t)aidx*4;
        const float* r = reg + ((size_t)b*A + aidx)*4;
        float a0 = a[0], a1 = a[1], a2 = a[2], a3 = a[3];
        float cx = __fmul_rn(0.5f, __fadd_rn(a0, a2));
        float cy = __fmul_rn(0.5f, __fadd_rn(a1, a3));
        float w  = __fsub_rn(a2, a0);
        float hh = __fsub_rn(a3, a1);
        float x1 = __fsub_rn(cx, __fmul_rn(r[0], w));
        float y1 = __fsub_rn(cy, __fmul_rn(r[1], hh));
        float x2 = __fadd_rn(cx, __fmul_rn(r[2], w));
        float y2 = __fadd_rn(cy, __fmul_rn(r[3], hh));
        x1 = fminf(fmaxf(x1, 0.0f), IMGSZ);
        y1 = fminf(fmaxf(y1, 0.0f), IMGSZ);
        x2 = fminf(fmaxf(x2, 0.0f), IMGSZ);
        y2 = fminf(fmaxf(y2, 0.0f), IMGSZ);
        g_boxv[pos*4+0] = x1; g_boxv[pos*4+1] = y1;
        g_boxv[pos*4+2] = x2; g_boxv[pos*4+3] = y2;
    }
}

// fused per-image: merge ranking + stable class sort + warp NMS + final top-100
__global__ __launch_bounds__(1024) void k_post(float* __restrict__ out){
    extern __shared__ unsigned char dyn[];
    float*          sc     = (float*)(dyn + PO_SC);
    float*          ss     = (float*)(dyn + PO_SS);
    uint32_t*       wofs   = (uint32_t*)(dyn + PO_WOFS);
    uint32_t*       smaskA = (uint32_t*)(dyn + PO_SMASK);
    uint32_t*       ccls   = (uint32_t*)(dyn + PO_CCLS);
    uint32_t*       cstart = (uint32_t*)(dyn + PO_CSTART);
    unsigned short* r2p    = (unsigned short*)(dyn + PO_R2P);
    unsigned short* cord   = (unsigned short*)(dyn + PO_CORD);
    unsigned char*  labt   = (unsigned char*)(dyn + PO_LABT);
    unsigned char*  keepr  = (unsigned char*)(dyn + PO_KEEP);
    __shared__ int ps[1024];

    const int b = blockIdx.x, tid = threadIdx.x;
    const int w = tid >> 5, lane = tid & 31;

    // ---- stage scores + labels, init
    for (int t = tid; t < CAND; t += 1024){
        sc[t]   = g_score[b*CAND + t];
        labt[t] = (unsigned char)g_labelv[b*CAND + t];
        keepr[t] = 1;
    }
    for (int i = tid; i < 32*NC; i += 1024) wofs[i] = 0;
    __syncthreads();

    // ---- merge: global rank via binary searches (exact top_k tie rules)
    for (int t = tid; t < CAND; t += 1024){
        int l = t / TOPK;
        float x = sc[t];
        int rank = t % TOPK;
        #pragma unroll
        for (int l2 = 0; l2 < NLVL; ++l2){
            if (l2 == l) continue;
            const float* arr = sc + l2*TOPK;
            int lo = 0, hi = TOPK;
            if (l2 < l){ while (lo < hi){ int m = (lo + hi) >> 1; if (arr[m] >= x) lo = m + 1; else hi = m; } }
            else       { while (lo < hi){ int m = (lo + hi) >> 1; if (arr[m] >  x) lo = m + 1; else hi = m; } }
            rank += lo;
        }
        r2p[rank] = (unsigned short)t;
        ss[rank]  = x;
    }
    __syncthreads();

    // ---- counting sort by class (stable in rank order)
    {   // per-warp per-class counts over the warp's contiguous rank chunk
        const int Rb = w*CHUNK;
        #pragma unroll
        for (int k = 0; k < 3; ++k){
            int o = k*32 + lane, r = Rb + o;
            if (o < CHUNK && r < CAND){
                int c = labt[r2p[r]];
                atomicAdd(&wofs[w*NC + c], 1u);
            }
        }
    }
    __syncthreads();
    if (tid < NC){          // per-class exclusive prefix across warps
        uint32_t run = 0;
        for (int ww = 0; ww < 32; ++ww){
            uint32_t t2 = wofs[ww*NC + tid];
            wofs[ww*NC + tid] = run;
            run += t2;
        }
        ccls[tid] = run;
    }
    __syncthreads();
    if (tid == 0){          // class segment starts
        uint32_t run = 0;
        for (int c = 0; c < NC; ++c){ uint32_t t2 = ccls[c]; cstart[c] = run; run += t2; }
    }
    __syncthreads();
    for (int i = tid; i < 32*NC; i += 1024) wofs[i] += cstart[i % NC];
    __syncthreads();
    {   // stable scatter (rounds sequential per warp; lane order = rank order)
        const int Rb = w*CHUNK;
        for (int k = 0; k < 3; ++k){
            int o = k*32 + lane, r = Rb + o;
            bool valid = (o < CHUNK) && (r < CAND);
            unsigned mask = __ballot_sync(0xFFFFFFFFu, valid);
            if (valid){
                int c = labt[r2p[r]];
                unsigned grp = __match_any_sync(mask, c);
                int leader = __ffs(grp) - 1;
                int pre = __popc(grp & ((1u << lane) - 1u));
                uint32_t old = 0;
                if (lane == leader) old = atomicAdd(&wofs[w*NC + c], (uint32_t)__popc(grp));
                old = __shfl_sync(grp, old, leader);
                cord[old + pre] = (unsigned short)r;
            }
        }
    }
    __syncthreads();

    // ---- warp-per-class NMS (offset rounding matches reference!)
    uint32_t* myMask = smaskA + w*(WCAP*4);
    for (int c = w; c < NC; c += 32){
        int cnt = (int)ccls[c];
        if (cnt == 0) continue;
        int start = (int)cstart[c];
        const float off = (float)c * 2049.0f;

        if (cnt <= WCAP){
            float bx1[4] = {0,0,0,0}, by1[4] = {0,0,0,0}, bx2[4] = {0,0,0,0}, by2[4] = {0,0,0,0};
            unsigned short rr[4] = {0,0,0,0};
            const int nw = (cnt + 31) >> 5;
            #pragma unroll
            for (int k = 0; k < 4; ++k){
                int j = lane + 32*k;
                if (j < cnt){
                    int r = cord[start + j];
                    rr[k] = (unsigned short)r;
                    int pos = r2p[r];
                    const float* bp = g_boxv + ((size_t)b*CAND + pos)*4;
                    bx1[k] = __fadd_rn(bp[0], off);
                    by1[k] = __fadd_rn(bp[1], off);
                    bx2[k] = __fadd_rn(bp[2], off);
                    by2[k] = __fadd_rn(bp[3], off);
                }
            }
            // build suppress-bitmask rows: row i = {j > i : iou > thr}
            for (int i = 0; i < cnt; ++i){
                const int slot = i >> 5, src = i & 31;
                float ix1 = __shfl_sync(0xFFFFFFFFu, pick4(bx1, slot), src);
                float iy1 = __shfl_sync(0xFFFFFFFFu, pick4(by1, slot), src);
                float ix2 = __shfl_sync(0xFFFFFFFFu, pick4(bx2, slot), src);
                float iy2 = __shfl_sync(0xFFFFFFFFu, pick4(by2, slot), src);
                float ia = __fmul_rn(__fsub_rn(ix2, ix1), __fsub_rn(iy2, iy1));
                #pragma unroll
                for (int k = 0; k < 4; ++k){
                    if (k >= slot && k < nw){
                        int j = lane + 32*k;
                        bool sup = false;
                        if (j > i && j < cnt){
                            float xx1 = fmaxf(ix1, bx1[k]), yy1 = fmaxf(iy1, by1[k]);
                            float xx2 = fminf(ix2, bx2[k]), yy2 = fminf(iy2, by2[k]);
                            float ww = fmaxf(__fsub_rn(xx2, xx1), 0.0f);
                            float hh = fmaxf(__fsub_rn(yy2, yy1), 0.0f);
                            float inter = __fmul_rn(ww, hh);
                            float ma  = __fmul_rn(__fsub_rn(bx2[k], bx1[k]), __fsub_rn(by2[k], by1[k]));
                            float uni = __fsub_rn(__fadd_rn(ia, ma), inter);
                            sup = (inter / uni > NMS_T);
                        }
                        unsigned bal = __ballot_sync(0xFFFFFFFFu, sup);
                        if (lane == 0) myMask[i*4 + k] = bal;
                    }
                }
            }
            __syncwarp();
            // scalar greedy bitmask scan (replicated; broadcast shared reads)
            uint32_t sup[4] = {0,0,0,0};
            for (int i = 0; i < cnt; ++i){
                int wi = i >> 5;
                if (!((sup[wi] >> (i & 31)) & 1u)){
                    #pragma unroll
                    for (int k = 0; k < 4; ++k)
                        if (k >= wi && k < nw) sup[k] |= myMask[i*4 + k];
                }
            }
            #pragma unroll
            for (int k = 0; k < 4; ++k){
                int j = lane + 32*k;
                if (j < cnt) keepr[rr[k]] = (unsigned char)(((~sup[k]) >> lane) & 1u);
            }
        } else {
            // serial fallback (not expected): greedy from global
            for (int i = 0; i < cnt; ++i){
                int ri = cord[start + i];
                if (keepr[ri]){
                    int posi = r2p[ri];
                    const float* bp = g_boxv + ((size_t)b*CAND + posi)*4;
                    float ix1 = __fadd_rn(bp[0], off), iy1 = __fadd_rn(bp[1], off);
                    float ix2 = __fadd_rn(bp[2], off), iy2 = __fadd_rn(bp[3], off);
                    float ia = __fmul_rn(__fsub_rn(ix2, ix1), __fsub_rn(iy2, iy1));
                    for (int m = i + 1 + lane; m < cnt; m += 32){
                        int rm = cord[start + m];
                        if (!keepr[rm]) continue;
                        int pos = r2p[rm];
                        const float* mp = g_boxv + ((size_t)b*CAND + pos)*4;
                        float mx1 = __fadd_rn(mp[0], off), my1 = __fadd_rn(mp[1], off);
                        float mx2 = __fadd_rn(mp[2], off), my2 = __fadd_rn(mp[3], off);
                        float xx1 = fmaxf(ix1, mx1), yy1 = fmaxf(iy1, my1);
                        float xx2 = fminf(ix2, mx2), yy2 = fminf(iy2, my2);
                        float ww = fmaxf(__fsub_rn(xx2, xx1), 0.0f);
                        float hh = fmaxf(__fsub_rn(yy2, yy1), 0.0f);
                        float inter = __fmul_rn(ww, hh);
                        float ma  = __fmul_rn(__fsub_rn(mx2, mx1), __fsub_rn(my2, my1));
                        float uni = __fsub_rn(__fadd_rn(ia, ma), inter);
                        if (inter / uni > NMS_T) keepr[rm] = 0;
                    }
                }
                __syncwarp();
            }
        }
    }
    __syncthreads();

    // ---- final: top-100 kept (rank order), pad with non-kept (rank order, score -1)
    int flags[3]; int loc = 0;
    #pragma unroll
    for (int u = 0; u < 3; ++u){
        int r = tid*3 + u;
        int f = 0;
        if (r < CAND) f = (keepr[r] && (ss[r] > 0.0f)) ? 1 : 0;
        flags[u] = f; loc += f;
    }
    ps[tid] = loc; __syncthreads();
    for (int o = 1; o < 1024; o <<= 1){
        int t = (tid >= o) ? ps[tid - o] : 0;
        __syncthreads();
        ps[tid] += t;
        __syncthreads();
    }
    const int excl  = ps[tid] - loc;
    const int total = ps[1023];

    int s = excl;
    #pragma unroll
    for (int u = 0; u < 3; ++u){
        int r = tid*3 + u;
        if (r < CAND && flags[u]){
            if (s < DETS){
                int pos = r2p[r];
                const float* bp = g_boxv + ((size_t)b*CAND + pos)*4;
                float* ob = out + ((size_t)b*DETS + s)*4;
                ob[0] = bp[0]; ob[1] = bp[1]; ob[2] = bp[2]; ob[3] = bp[3];
                out[NB*DETS*4 + b*DETS + s]           = ss[r];
                out[NB*DETS*4 + NB*DETS + b*DETS + s] = (float)labt[pos];
            }
            s++;
        }
    }
    const int base = (total < DETS) ? total : DETS;
    __syncthreads();

    loc = 0; int pflags[3];
    #pragma unroll
    for (int u = 0; u < 3; ++u){
        int r = tid*3 + u;
        int f = (r < CAND && !flags[u]) ? 1 : 0;
        pflags[u] = f; loc += f;
    }
    ps[tid] = loc; __syncthreads();
    for (int o = 1; o < 1024; o <<= 1){
        int t = (tid >= o) ? ps[tid - o] : 0;
        __syncthreads();
        ps[tid] += t;
        __syncthreads();
    }
    int pexcl = ps[tid] - loc;
    s = base + pexcl;
    #pragma unroll
    for (int u = 0; u < 3; ++u){
        int r = tid*3 + u;
        if (r < CAND && pflags[u]){
            if (s < DETS){
                int pos = r2p[r];
                const float* bp = g_boxv + ((size_t)b*CAND + pos)*4;
                float* ob = out + ((size_t)b*DETS + s)*4;
                ob[0] = bp[0]; ob[1] = bp[1]; ob[2] = bp[2]; ob[3] = bp[3];
                out[NB*DETS*4 + b*DETS + s]           = -1.0f;
                out[NB*DETS*4 + NB*DETS + b*DETS + s] = (float)labt[pos];
            }
            s++;
        }
    }
}

// ---------------- host ----------------
extern "C" void kernel_launch(void* const* d_in, const int* in_sizes, int n_in,
                              void* d_out, int out_size){
    const float *cls[3], *reg[3], *ctr[3], *anc[3];
    if (n_in >= 12 && in_sizes[0] == 2621440 && in_sizes[1] == 131072){
        for (int l = 0; l < 3; ++l){
            cls[l] = (const float*)d_in[4*l + 0];
            reg[l] = (const float*)d_in[4*l + 1];
            ctr[l] = (const float*)d_in[4*l + 2];
            anc[l] = (const float*)d_in[4*l + 3];
        }
    } else if (n_in >= 12 && in_sizes[0] == 16384){
        for (int l = 0; l < 3; ++l){
            anc[l] = (const float*)d_in[0 + l];
            cls[l] = (const float*)d_in[3 + l];
            ctr[l] = (const float*)d_in[6 + l];
            reg[l] = (const float*)d_in[9 + l];
        }
    } else {
        for (int l = 0; l < 3; ++l){
            cls[l] = (const float*)d_in[0 + l];
            reg[l] = (const float*)d_in[3 + l];
            ctr[l] = (const float*)d_in[6 + l];
            anc[l] = (const float*)d_in[9 + l];
        }
    }

    static int attr_done = 0;
    if (!attr_done){
        cudaFuncSetAttribute(k_sortlevel, cudaFuncAttributeMaxDynamicSharedMemorySize, DYNBYTES);
        cudaFuncSetAttribute(k_post, cudaFuncAttributeMaxDynamicSharedMemorySize, POSTBYTES);
        attr_done = 1;
    }

    k_scores<<<dim3(TOT/2048, NB), 256>>>(cls[0], cls[1], cls[2], ctr[0], ctr[1], ctr[2]);
    k_sortlevel<<<NPAIR, 1024, DYNBYTES>>>(cls[0], cls[1], cls[2], ctr[0], ctr[1], ctr[2],
                                           reg[0], reg[1], reg[2], anc[0], anc[1], anc[2]);
    k_post<<<NB, 1024, POSTBYTES>>>((float*)d_out);
}

// round 9
// speedup vs baseline: 1.3908x; 1.3908x over previous
#include <cuda_runtime.h>
#include <stdint.h>

// ---------------- problem constants ----------------
#define NC    80
#define A0    4096
#define A1    1024
#define A2    256
#define N0    (A0*NC)          // 327680
#define N1    (A1*NC)          // 81920
#define N2    (A2*NC)          // 20480
#define TOT   (N0+N1+N2)       // 430080 per image
#define OFF1  N0
#define OFF2  (N0+N1)
#define NB    8
#define TOPK  1000
#define NLVL  3
#define NPAIR (NB*NLVL)        // 24
#define CAND  3000
#define DETS  100
#define IMGSZ 2048.0f
#define NMS_T 0.6f
#define CAP   4096
#define BINS  16512            // key16 range: ~f2k(w>=1) >> 16 in [127, 16511]
#define WCAP  128              // bitmask fast-path capacity per class (avg ~37)
#define CHUNK 94               // ranks per warp in counting sort (32*94 >= 3000)

// dynamic smem for k_sortlevel: union of hist (BINS u32) and sort buffer (CAP u64)
#define DYNBYTES ((BINS*4 > CAP*8) ? BINS*4 : CAP*8)

// k_post dynamic smem layout (bytes)
#define PO_SC     0          // float sc[3008]
#define PO_SS     12032      // float ss[3008]
#define PO_BX     24064      // float bx[3008*4]  (class-ordered offset boxes)
#define PO_MASK   72192      // u32 smask[12032]  (4 words per class-order row)
#define PO_WOFS   120320     // u32 wofs[32*80]
#define PO_CCLS   130560     // u32 ccls[80]
#define PO_CSTART 130880     // u32 cstart[80]
#define PO_R2P    131200     // u16 r2p[3008]
#define PO_CORD   137216     // u16 cord[3008]
#define PO_LABT   143232     // u8 labt[3008]
#define PO_KEEP   146240     // u8 keepr[3008]
#define POSTBYTES 149248

// ---------------- scratch (device globals; no allocations) ----------------
__device__ __align__(16) unsigned short g_keys16[NB*TOT]; // ~6.9 MB
__device__ float    g_score[NB*CAND];
__device__ int      g_labelv[NB*CAND];
__device__ float    g_boxv[NB*CAND*4];

// ---------------- helpers ----------------
__device__ __forceinline__ uint32_t f2k(float f){
    uint32_t u = __float_as_uint(f);
    return (u & 0x80000000u) ? ~u : (u | 0x80000000u);
}
__device__ __forceinline__ float k2f(uint32_t k){
    uint32_t u = (k & 0x80000000u) ? (k ^ 0x80000000u) : ~k;
    return __uint_as_float(u);
}
// exact path: XLA logistic(x) == 0.5 + 0.5*tanh(0.5*x)
__device__ __forceinline__ float sigm(float x){
    return 0.5f*tanhf(0.5f*x) + 0.5f;
}

// bitonic sort (ascending) of n (2048 or 4096) u64s, blockDim = 1024
__device__ __forceinline__ void bitonicN(unsigned long long* s, int n){
    const int tid = threadIdx.x;
    const int per = n >> 10;
    for (int k = 2; k <= n; k <<= 1){
        for (int j = k >> 1; j > 0; j >>= 1){
            __syncthreads();
            for (int w = 0; w < per; ++w){
                int i   = tid + (w << 10);
                int ixj = i ^ j;
                if (ixj > i){
                    unsigned long long a = s[i], bb = s[ixj];
                    bool up = ((i & k) == 0);
                    if ((a > bb) == up){ s[i] = bb; s[ixj] = a; }
                }
            }
        }
    }
    __syncthreads();
}

// ---------------- kernels ----------------
// pure streaming pass: surrogate 16-bit keys, NO atomics
// surrogate: w = (1+e^-c)(1+e^-t); score order == descending w (monotone)
__global__ __launch_bounds__(256) void k_scores(
    const float* __restrict__ cls0, const float* __restrict__ cls1, const float* __restrict__ cls2,
    const float* __restrict__ ctr0, const float* __restrict__ ctr1, const float* __restrict__ ctr2)
{
    const int b = blockIdx.y;
    const int base = blockIdx.x*2048 + threadIdx.x*8;   // blocks never straddle levels; 8-runs never straddle anchors
    int j0, A; const float* cls; const float* ctr;
    if (base < OFF1){ j0 = base;        cls = cls0; ctr = ctr0; A = A0; }
    else if (base < OFF2){ j0 = base - OFF1; cls = cls1; ctr = ctr1; A = A1; }
    else { j0 = base - OFF2; cls = cls2; ctr = ctr2; A = A2; }

    float tv = __ldg(ctr + (size_t)b*A + j0/NC);
    float et = __expf(-tv);
    float vt = et + 1.0f;

    const float4* cp = (const float4*)(cls + (size_t)b*A*NC + j0);
    float4 ca = cp[0], cb = cp[1];
    float cv[8] = {ca.x, ca.y, ca.z, ca.w, cb.x, cb.y, cb.z, cb.w};

    uint32_t ks[8];
    #pragma unroll
    for (int e = 0; e < 8; ++e){
        float ec = __expf(-cv[e]);
        float w  = fmaf(ec, vt, vt);                        // (1+ec)*vt
        ks[e] = ((~__float_as_uint(w)) & 0x7FFFFFFFu) >> 16; // = ~f2k(w)>>16, w>0
    }
    uint4 pk;
    pk.x = ks[0] | (ks[1] << 16);
    pk.y = ks[2] | (ks[3] << 16);
    pk.z = ks[4] | (ks[5] << 16);
    pk.w = ks[6] | (ks[7] << 16);
    *(uint4*)(g_keys16 + (size_t)b*TOT + base) = pk;
}

// per (image,level): shared hist + pivot + collect + exact rescore + sort + decode top-1000
__global__ __launch_bounds__(1024) void k_sortlevel(
    const float* __restrict__ cls0, const float* __restrict__ cls1, const float* __restrict__ cls2,
    const float* __restrict__ ctr0, const float* __restrict__ ctr1, const float* __restrict__ ctr2,
    const float* __restrict__ reg0, const float* __restrict__ reg1, const float* __restrict__ reg2,
    const float* __restrict__ anc0, const float* __restrict__ anc1, const float* __restrict__ anc2)
{
    extern __shared__ unsigned char dynsmem[];
    uint32_t*           hist = (uint32_t*)dynsmem;           // phase A (BINS u32)
    unsigned long long* s64  = (unsigned long long*)dynsmem; // phase B+ (CAP u64), aliases hist
    __shared__ uint32_t ssum[1024];
    __shared__ int sP, sCum, sThresh, sCnt;

    const int p = blockIdx.x, b = p/NLVL, l = p%NLVL;
    const int tid = threadIdx.x;
    int A, offl; const float *cls, *ctr, *reg, *anc;
    if (l == 0){ A=A0; offl=0;    cls=cls0; ctr=ctr0; reg=reg0; anc=anc0; }
    else if (l == 1){ A=A1; offl=OFF1; cls=cls1; ctr=ctr1; reg=reg1; anc=anc1; }
    else { A=A2; offl=OFF2; cls=cls2; ctr=ctr2; reg=reg2; anc=anc2; }

    // ---- phase H: build local histogram from this pair's key slice (L2-resident)
    for (int t = tid; t < BINS; t += 1024) hist[t] = 0;
    __syncthreads();
    const uint4* kp = (const uint4*)(g_keys16 + (size_t)b*TOT + offl);
    const int num8 = (A*NC)/8;
    for (int v = tid; v < num8; v += 1024){
        uint4 q = kp[v];
        uint32_t wv[4] = {q.x, q.y, q.z, q.w};
        #pragma unroll
        for (int u = 0; u < 4; ++u){
            atomicAdd(hist + (wv[u] & 0xFFFFu), 1u);
            atomicAdd(hist + (wv[u] >> 16),     1u);
        }
    }
    __syncthreads();

    // ---- phase A: pivot bin (highest T with cum(bins>=T) >= TOPK), extend 1 bin if safe
    int lo = tid*17; if (lo > BINS) lo = BINS;
    int hi = lo + 17; if (hi > BINS) hi = BINS;
    uint32_t own = 0;
    for (int i = lo; i < hi; ++i) own += hist[i];
    ssum[tid] = own; __syncthreads();
    for (int off = 1; off < 1024; off <<= 1){
        uint32_t v = (tid + off < 1024) ? ssum[tid + off] : 0;
        __syncthreads(); ssum[tid] += v; __syncthreads();
    }
    uint32_t cumAbove = (tid < 1023) ? ssum[tid + 1] : 0;
    if (tid == 0) sCnt = 0;
    if (cumAbove < TOPK && cumAbove + own >= TOPK){
        uint32_t run = cumAbove; int P = lo;
        for (int i = hi - 1; i >= lo; --i){ run += hist[i]; if (run >= TOPK){ P = i; break; } }
        sP = P; sCum = (int)run;
    }
    __syncthreads();
    if (tid == 0){
        int P = sP, ext = P;
        if (P > 0 && sCum + (int)hist[P-1] <= CAP) ext = P - 1;
        sThresh = ext;
    }
    __syncthreads();
    const uint32_t thr = (uint32_t)sThresh;
    __syncthreads();   // all hist reads done before s64 overwrites it

    // ---- phase B: collect candidate indices (order arbitrary; fixed by sort)
    for (int v = tid; v < num8; v += 1024){
        uint4 q = kp[v];
        uint32_t wv[4] = {q.x, q.y, q.z, q.w};
        #pragma unroll
        for (int u = 0; u < 4; ++u){
            uint32_t l16 = wv[u] & 0xFFFFu, h16 = wv[u] >> 16;
            if (l16 >= thr){ int pos = atomicAdd(&sCnt, 1); if (pos < CAP) s64[pos] = (unsigned long long)(v*8 + u*2); }
            if (h16 >= thr){ int pos = atomicAdd(&sCnt, 1); if (pos < CAP) s64[pos] = (unsigned long long)(v*8 + u*2 + 1); }
        }
    }
    __syncthreads();
    int cnt = sCnt; if (cnt > CAP) cnt = CAP;
    const int SORTN = (cnt <= 2048) ? 2048 : 4096;

    // ---- phase C: exact XLA-matching scores; build (~key, idx) composites
    for (int i = tid; i < SORTN; i += 1024){
        unsigned long long comp = 0xFFFFFFFFFFFFFFFFULL;
        if (i < cnt){
            int j = (int)(uint32_t)s64[i];
            float c  = cls[(size_t)b*A*NC + j];
            float tt = ctr[(size_t)b*A + j/NC];
            float sa = sigm(c);
            float st = sigm(tt);
            float sc = sqrtf(__fmul_rn(sa, st));
            uint32_t key = (sc > 0.2f) ? f2k(sc) : 0x407FFFFFu;   // f2k(-1.0f)
            comp = ((unsigned long long)(~key) << 32) | (uint32_t)j;
        }
        s64[i] = comp;
    }
    bitonicN(s64, SORTN);

    // ---- phase E: emit sorted top-1000 + decode boxes
    if (tid < TOPK){
        unsigned long long cc = s64[tid];
        uint32_t key = ~(uint32_t)(cc >> 32);
        uint32_t idx = (uint32_t)cc;
        float sc = k2f(key);
        int aidx = (int)(idx / NC);
        int lab  = (int)(idx % NC);

        const int pos = b*CAND + l*TOPK + tid;
        g_score[pos]  = sc;
        g_labelv[pos] = lab;

        const float* a = anc + (size_t)aidx*4;
        const float* r = reg + ((size_t)b*A + aidx)*4;
        float a0 = a[0], a1 = a[1], a2 = a[2], a3 = a[3];
        float cx = __fmul_rn(0.5f, __fadd_rn(a0, a2));
        float cy = __fmul_rn(0.5f, __fadd_rn(a1, a3));
        float w  = __fsub_rn(a2, a0);
        float hh = __fsub_rn(a3, a1);
        float x1 = __fsub_rn(cx, __fmul_rn(r[0], w));
        float y1 = __fsub_rn(cy, __fmul_rn(r[1], hh));
        float x2 = __fadd_rn(cx, __fmul_rn(r[2], w));
        float y2 = __fadd_rn(cy, __fmul_rn(r[3], hh));
        x1 = fminf(fmaxf(x1, 0.0f), IMGSZ);
        y1 = fminf(fmaxf(y1, 0.0f), IMGSZ);
        x2 = fminf(fmaxf(x2, 0.0f), IMGSZ);
        y2 = fminf(fmaxf(y2, 0.0f), IMGSZ);
        g_boxv[pos*4+0] = x1; g_boxv[pos*4+1] = y1;
        g_boxv[pos*4+2] = x2; g_boxv[pos*4+3] = y2;
    }
}

// fused per-image: merge ranking + stable class sort + BLOCK-PARALLEL NMS + final top-100
__global__ __launch_bounds__(1024) void k_post(float* __restrict__ out){
    extern __shared__ unsigned char dyn[];
    float*          sc     = (float*)(dyn + PO_SC);
    float*          ss     = (float*)(dyn + PO_SS);
    float*          bx     = (float*)(dyn + PO_BX);
    uint32_t*       smask  = (uint32_t*)(dyn + PO_MASK);
    uint32_t*       wofs   = (uint32_t*)(dyn + PO_WOFS);
    uint32_t*       ccls   = (uint32_t*)(dyn + PO_CCLS);
    uint32_t*       cstart = (uint32_t*)(dyn + PO_CSTART);
    unsigned short* r2p    = (unsigned short*)(dyn + PO_R2P);
    unsigned short* cord   = (unsigned short*)(dyn + PO_CORD);
    unsigned char*  labt   = (unsigned char*)(dyn + PO_LABT);
    unsigned char*  keepr  = (unsigned char*)(dyn + PO_KEEP);
    __shared__ int ps[1024];

    const int b = blockIdx.x, tid = threadIdx.x;
    const int w = tid >> 5, lane = tid & 31;

    // ---- stage scores + labels, init
    for (int t = tid; t < CAND; t += 1024){
        sc[t]   = g_score[b*CAND + t];
        labt[t] = (unsigned char)g_labelv[b*CAND + t];
        keepr[t] = 1;
    }
    for (int i = tid; i < 32*NC; i += 1024) wofs[i] = 0;
    __syncthreads();

    // ---- merge: global rank via binary searches (exact top_k tie rules)
    for (int t = tid; t < CAND; t += 1024){
        int l = t / TOPK;
        float x = sc[t];
        int rank = t % TOPK;
        #pragma unroll
        for (int l2 = 0; l2 < NLVL; ++l2){
            if (l2 == l) continue;
            const float* arr = sc + l2*TOPK;
            int lo = 0, hi = TOPK;
            if (l2 < l){ while (lo < hi){ int m = (lo + hi) >> 1; if (arr[m] >= x) lo = m + 1; else hi = m; } }
            else       { while (lo < hi){ int m = (lo + hi) >> 1; if (arr[m] >  x) lo = m + 1; else hi = m; } }
            rank += lo;
        }
        r2p[rank] = (unsigned short)t;
        ss[rank]  = x;
    }
    __syncthreads();

    // ---- counting sort by class (stable in rank order)
    {   // per-warp per-class counts over the warp's contiguous rank chunk
        const int Rb = w*CHUNK;
        #pragma unroll
        for (int k = 0; k < 3; ++k){
            int o = k*32 + lane, r = Rb + o;
            if (o < CHUNK && r < CAND){
                int c = labt[r2p[r]];
                atomicAdd(&wofs[w*NC + c], 1u);
            }
        }
    }
    __syncthreads();
    if (tid < NC){          // per-class exclusive prefix across warps
        uint32_t run = 0;
        for (int ww = 0; ww < 32; ++ww){
            uint32_t t2 = wofs[ww*NC + tid];
            wofs[ww*NC + tid] = run;
            run += t2;
        }
        ccls[tid] = run;
    }
    __syncthreads();
    if (tid == 0){          // class segment starts
        uint32_t run = 0;
        for (int c = 0; c < NC; ++c){ uint32_t t2 = ccls[c]; cstart[c] = run; run += t2; }
    }
    __syncthreads();
    for (int i = tid; i < 32*NC; i += 1024) wofs[i] += cstart[i % NC];
    __syncthreads();
    {   // stable scatter (rounds sequential per warp; lane order = rank order)
        const int Rb = w*CHUNK;
        for (int k = 0; k < 3; ++k){
            int o = k*32 + lane, r = Rb + o;
            bool valid = (o < CHUNK) && (r < CAND);
            unsigned mask = __ballot_sync(0xFFFFFFFFu, valid);
            if (valid){
                int c = labt[r2p[r]];
                unsigned grp = __match_any_sync(mask, c);
                int leader = __ffs(grp) - 1;
                int pre = __popc(grp & ((1u << lane) - 1u));
                uint32_t old = 0;
                if (lane == leader) old = atomicAdd(&wofs[w*NC + c], (uint32_t)__popc(grp));
                old = __shfl_sync(grp, old, leader);
                cord[old + pre] = (unsigned short)r;
            }
        }
    }
    __syncthreads();

    // ---- stage class-ordered OFFSET boxes to shared (offset rounding matches reference!)
    for (int m = tid; m < CAND; m += 1024){
        int r   = cord[m];
        int pos = r2p[r];
        float off = (float)labt[pos] * 2049.0f;
        const float* bp = g_boxv + ((size_t)b*CAND + pos)*4;
        bx[m*4+0] = __fadd_rn(bp[0], off);
        bx[m*4+1] = __fadd_rn(bp[1], off);
        bx[m*4+2] = __fadd_rn(bp[2], off);
        bx[m*4+3] = __fadd_rn(bp[3], off);
    }
    __syncthreads();

    // ---- mask build: one THREAD per class-order row (no warp collectives)
    for (int m = tid; m < CAND; m += 1024){
        int c     = labt[r2p[cord[m]]];
        int start = (int)cstart[c];
        int cnt   = (int)ccls[c];
        if (cnt > WCAP) continue;             // fallback handles
        int i = m - start;
        float ix1 = bx[m*4+0], iy1 = bx[m*4+1], ix2 = bx[m*4+2], iy2 = bx[m*4+3];
        float ia = __fmul_rn(__fsub_rn(ix2, ix1), __fsub_rn(iy2, iy1));
        int nw = (cnt + 31) >> 5;
        for (int k = (i >> 5); k < nw; ++k){
            uint32_t wm = 0;
            int j0 = k << 5;
            int jend = cnt - j0; if (jend > 32) jend = 32;
            for (int u = 0; u < jend; ++u){
                int j = j0 + u;
                if (j > i){
                    int q = (start + j)*4;
                    float mx1 = bx[q], my1 = bx[q+1], mx2 = bx[q+2], my2 = bx[q+3];
                    float xx1 = fmaxf(ix1, mx1), yy1 = fmaxf(iy1, my1);
                    float xx2 = fminf(ix2, mx2), yy2 = fminf(iy2, my2);
                    float ww = fmaxf(__fsub_rn(xx2, xx1), 0.0f);
                    float hh = fmaxf(__fsub_rn(yy2, yy1), 0.0f);
                    float inter = __fmul_rn(ww, hh);
                    float ma  = __fmul_rn(__fsub_rn(mx2, mx1), __fsub_rn(my2, my1));
                    float uni = __fsub_rn(__fadd_rn(ia, ma), inter);
                    if (inter / uni > NMS_T) wm |= (1u << u);
                }
            }
            smask[m*4 + k] = wm;
        }
    }
    __syncthreads();

    // ---- greedy bitmask scan: one THREAD per class (all 80 in parallel)
    if (tid < NC){
        int cnt = (int)ccls[tid];
        if (cnt > 0 && cnt <= WCAP){
            int start = (int)cstart[tid];
            int nw = (cnt + 31) >> 5;
            uint32_t s0 = 0, s1 = 0, s2 = 0, s3 = 0;
            for (int i = 0; i < cnt; ++i){
                int wi = i >> 5;
                uint32_t cur = (wi == 0) ? s0 : (wi == 1) ? s1 : (wi == 2) ? s2 : s3;
                if (!((cur >> (i & 31)) & 1u)){
                    int base = (start + i)*4;
                    if (0 >= wi && 0 < nw) s0 |= smask[base + 0];
                    if (1 >= wi && 1 < nw) s1 |= smask[base + 1];
                    if (2 >= wi && 2 < nw) s2 |= smask[base + 2];
                    if (3 >= wi && 3 < nw) s3 |= smask[base + 3];
                }
            }
            for (int j = 0; j < cnt; ++j){
                int wj = j >> 5;
                uint32_t sv = (wj == 0) ? s0 : (wj == 1) ? s1 : (wj == 2) ? s2 : s3;
                keepr[cord[start + j]] = (unsigned char)(((~sv) >> (j & 31)) & 1u);
            }
        }
    }
    __syncthreads();

    // ---- fallback for huge classes (cnt > WCAP): warp 0, serial greedy on shared boxes
    if (w == 0){
        for (int c = 0; c < NC; ++c){
            int cnt = (int)ccls[c];
            if (cnt <= WCAP) continue;
            int start = (int)cstart[c];
            for (int i = 0; i < cnt; ++i){
                if (keepr[cord[start + i]]){
                    float ix1 = bx[(start+i)*4+0], iy1 = bx[(start+i)*4+1];
                    float ix2 = bx[(start+i)*4+2], iy2 = bx[(start+i)*4+3];
                    float ia = __fmul_rn(__fsub_rn(ix2, ix1), __fsub_rn(iy2, iy1));
                    for (int m = i + 1 + lane; m < cnt; m += 32){
                        if (!keepr[cord[start + m]]) continue;
                        float mx1 = bx[(start+m)*4+0], my1 = bx[(start+m)*4+1];
                        float mx2 = bx[(start+m)*4+2], my2 = bx[(start+m)*4+3];
                        float xx1 = fmaxf(ix1, mx1), yy1 = fmaxf(iy1, my1);
                        float xx2 = fminf(ix2, mx2), yy2 = fminf(iy2, my2);
                        float ww = fmaxf(__fsub_rn(xx2, xx1), 0.0f);
                        float hh = fmaxf(__fsub_rn(yy2, yy1), 0.0f);
                        float inter = __fmul_rn(ww, hh);
                        float ma  = __fmul_rn(__fsub_rn(mx2, mx1), __fsub_rn(my2, my1));
                        float uni = __fsub_rn(__fadd_rn(ia, ma), inter);
                        if (inter / uni > NMS_T) keepr[cord[start + m]] = 0;
                    }
                }
                __syncwarp();
            }
        }
    }
    __syncthreads();

    // ---- final: top-100 kept (rank order), pad with non-kept (rank order, score -1)
    int flags[3]; int loc = 0;
    #pragma unroll
    for (int u = 0; u < 3; ++u){
        int r = tid*3 + u;
        int f = 0;
        if (r < CAND) f = (keepr[r] && (ss[r] > 0.0f)) ? 1 : 0;
        flags[u] = f; loc += f;
    }
    ps[tid] = loc; __syncthreads();
    for (int o = 1; o < 1024; o <<= 1){
        int t = (tid >= o) ? ps[tid - o] : 0;
        __syncthreads();
        ps[tid] += t;
        __syncthreads();
    }
    const int excl  = ps[tid] - loc;
    const int total = ps[1023];

    int s = excl;
    #pragma unroll
    for (int u = 0; u < 3; ++u){
        int r = tid*3 + u;
        if (r < CAND && flags[u]){
            if (s < DETS){
                int pos = r2p[r];
                const float* bp = g_boxv + ((size_t)b*CAND + pos)*4;
                float* ob = out + ((size_t)b*DETS + s)*4;
                ob[0] = bp[0]; ob[1] = bp[1]; ob[2] = bp[2]; ob[3] = bp[3];
                out[NB*DETS*4 + b*DETS + s]           = ss[r];
                out[NB*DETS*4 + NB*DETS + b*DETS + s] = (float)labt[pos];
            }
            s++;
        }
    }
    const int base = (total < DETS) ? total : DETS;
    __syncthreads();

    loc = 0; int pflags[3];
    #pragma unroll
    for (int u = 0; u < 3; ++u){
        int r = tid*3 + u;
        int f = (r < CAND && !flags[u]) ? 1 : 0;
        pflags[u] = f; loc += f;
    }
    ps[tid] = loc; __syncthreads();
    for (int o = 1; o < 1024; o <<= 1){
        int t = (tid >= o) ? ps[tid - o] : 0;
        __syncthreads();
        ps[tid] += t;
        __syncthreads();
    }
    int pexcl = ps[tid] - loc;
    s = base + pexcl;
    #pragma unroll
    for (int u = 0; u < 3; ++u){
        int r = tid*3 + u;
        if (r < CAND && pflags[u]){
            if (s < DETS){
                int pos = r2p[r];
                const float* bp = g_boxv + ((size_t)b*CAND + pos)*4;
                float* ob = out + ((size_t)b*DETS + s)*4;
                ob[0] = bp[0]; ob[1] = bp[1]; ob[2] = bp[2]; ob[3] = bp[3];
                out[NB*DETS*4 + b*DETS + s]           = -1.0f;
                out[NB*DETS*4 + NB*DETS + b*DETS + s] = (float)labt[pos];
            }
            s++;
        }
    }
}

// ---------------- host ----------------
extern "C" void kernel_launch(void* const* d_in, const int* in_sizes, int n_in,
                              void* d_out, int out_size){
    const float *cls[3], *reg[3], *ctr[3], *anc[3];
    if (n_in >= 12 && in_sizes[0] == 2621440 && in_sizes[1] == 131072){
        for (int l = 0; l < 3; ++l){
            cls[l] = (const float*)d_in[4*l + 0];
            reg[l] = (const float*)d_in[4*l + 1];
            ctr[l] = (const float*)d_in[4*l + 2];
            anc[l] = (const float*)d_in[4*l + 3];
        }
    } else if (n_in >= 12 && in_sizes[0] == 16384){
        for (int l = 0; l < 3; ++l){
            anc[l] = (const float*)d_in[0 + l];
            cls[l] = (const float*)d_in[3 + l];
            ctr[l] = (const float*)d_in[6 + l];
            reg[l] = (const float*)d_in[9 + l];
        }
    } else {
        for (int l = 0; l < 3; ++l){
            cls[l] = (const float*)d_in[0 + l];
            reg[l] = (const float*)d_in[3 + l];
            ctr[l] = (const float*)d_in[6 + l];
            anc[l] = (const float*)d_in[9 + l];
        }
    }

    static int attr_done = 0;
    if (!attr_done){
        cudaFuncSetAttribute(k_sortlevel, cudaFuncAttributeMaxDynamicSharedMemorySize, DYNBYTES);
        cudaFuncSetAttribute(k_post, cudaFuncAttributeMaxDynamicSharedMemorySize, POSTBYTES);
        attr_done = 1;
    }

    k_scores<<<dim3(TOT/2048, NB), 256>>>(cls[0], cls[1], cls[2], ctr[0], ctr[1], ctr[2]);
    k_sortlevel<<<NPAIR, 1024, DYNBYTES>>>(cls[0], cls[1], cls[2], ctr[0], ctr[1], ctr[2],
                                           reg[0], reg[1], reg[2], anc[0], anc[1], anc[2]);
    k_post<<<NB, 1024, POSTBYTES>>>((float*)d_out);
}